// round 11
// baseline (speedup 1.0000x reference)
#include <cuda_runtime.h>
#include <math.h>

#define NKEY 128            // NUM_IMGS(8) * NUM_CLASSES(16)
#define NUM_CLASSES 16
#define NB 128              // blocks (<=148 SMs -> co-resident, spin-safe)
#define NT 256              // threads per block
#define PPB 64              // points per block chunk (8192/128)
#define CAP 256             // slots per key

// ---- device scratch (no allocations; monotonic/self-resetting state) ----
__device__ float4 g_a[NKEY * CAP];   // {cx, cy, inv(2sig^2), score}
__device__ float2 g_v[NKEY * CAP];   // {cos4t, sin4t}
__device__ int    g_cnt[NKEY];       // zero at load; block b resets slot b in P2
__device__ int    g_bar;             // monotonic epoch barrier (never reset)
__device__ float  g_acc;             // zero at load; reset by finalize
__device__ int    g_done;            // zero at load; reset by finalize

__global__ __launch_bounds__(NT)
void k_fused(const float* __restrict__ preds,
             const float* __restrict__ scores,
             const int*   __restrict__ labels,
             const int*   __restrict__ batch,
             float* __restrict__ out, int n, float inv_n) {
    __shared__ float  sraw[PPB * 5];
    __shared__ float4 sa[CAP];
    __shared__ float2 sv[CAP];
    __shared__ float  red[NT / 32];

    const int t    = threadIdx.x;
    const int lane = t & 31;
    const int wib  = t >> 5;
    const int b    = blockIdx.x;

    // ---- P1: precompute + slotted scatter for this block's point chunk(s) ----
    for (int base = b * PPB; base < n; base += NB * PPB) {
        int cnt = min(PPB, n - base);
        // coalesced stage of 5-float records into smem
        for (int j = t; j < cnt * 5; j += NT)
            sraw[j] = preds[base * 5 + j];
        __syncthreads();
        if (t < cnt) {
            int i = base + t;
            float cx = sraw[5 * t],     cy = sraw[5 * t + 1];
            float w  = sraw[5 * t + 2], h  = sraw[5 * t + 3];
            float th = sraw[5 * t + 4];
            float scale = fminf(fmaxf(sqrtf(w * h), 16.0f), 800.0f);
            float sig = 2.0f * scale;                      // K_RADIUS = 2
            float inv = __fdividef(1.0f, 2.0f * sig * sig);
            float sn, cs;
            __sincosf(4.0f * th, &sn, &cs);                // |arg| <= 4*pi
            int key = batch[i] * NUM_CLASSES + labels[i];
            int slot = atomicAdd(&g_cnt[key], 1);
            if (slot < CAP) {
                g_a[key * CAP + slot] = make_float4(cx, cy, inv, scores[i]);
                g_v[key * CAP + slot] = make_float2(cs, sn);  // SCORE_ALPHA = 1
            }
        }
        __syncthreads();
    }

    // ---- monotonic epoch grid barrier (no reset -> replay-safe) ----
    __threadfence();                       // publish P1 writes
    if (t == 0) {
        int ticket = atomicAdd(&g_bar, 1);
        int target = (ticket / NB + 1) * NB;
        while (*(volatile int*)&g_bar < target) { }
    }
    __syncthreads();
    __threadfence();                       // acquire P1 writes

    // ---- P2: block b sweeps key b; 4 threads per point, warp-uniform loops ----
    const int mykey = b;
    int g = min(g_cnt[mykey], CAP);
    const int gbase = mykey * CAP;
    for (int j = t; j < g; j += NT) {
        sa[j] = g_a[gbase + j];
        sv[j] = g_v[gbase + j];
    }
    __syncthreads();
    if (t == 0) g_cnt[mykey] = 0;          // reset for next replay

    const int sub  = lane & 3;             // sub-thread within point (0..3)
    const int gpad = (g + 7) & ~7;         // warp-uniform outer bound
    float chaos = 0.0f;                    // accumulated on sub==0, valid p
    // each warp covers 8 points per pass: p = pb + (lane>>2)
    for (int pb = wib * 8; pb < gpad; pb += (NT / 32) * 8) {
        int p = pb + (lane >> 2);
        bool valid = (p < g);
        float4 a = sa[valid ? p : 0];
        float den = 0.0f, nx = 0.0f, ny = 0.0f;
        #pragma unroll 4
        for (int j = sub; j < g; j += 4) { // no collectives inside: divergence ok
            float4 bb = sa[j];
            float2 v  = sv[j];
            float dx = a.x - bb.x;
            float dy = a.y - bb.y;
            float wgt = __expf(-(dx * dx + dy * dy) * a.z) * bb.w;
            den += wgt;
            nx  += wgt * v.x;
            ny  += wgt * v.y;
        }
        // fold 4 sub-threads (adjacent lanes, same p) — warp-uniform
        #pragma unroll
        for (int o = 1; o < 4; o <<= 1) {
            den += __shfl_xor_sync(0xffffffffu, den, o);
            nx  += __shfl_xor_sync(0xffffffffu, nx, o);
            ny  += __shfl_xor_sync(0xffffffffu, ny, o);
        }
        if (valid && sub == 0)
            chaos += 1.0f - sqrtf(nx * nx + ny * ny) / den;
    }

    // ---- block reduce + global accumulate + last-block finalize ----
    float v = chaos;                       // nonzero only on sub==0 lanes
    #pragma unroll
    for (int o = 16; o >= 4; o >>= 1) v += __shfl_xor_sync(0xffffffffu, v, o);
    if (lane == 0) red[wib] = v;
    __syncthreads();
    if (t < NT / 32) {
        v = red[t];
        v += __shfl_xor_sync(0xffu, v, 4);
        v += __shfl_xor_sync(0xffu, v, 2);
        v += __shfl_xor_sync(0xffu, v, 1);
        if (t == 0) {
            atomicAdd(&g_acc, v);
            __threadfence();
            int tk = atomicAdd(&g_done, 1);
            if (tk == NB - 1) {                        // last block finalizes
                float tot = atomicAdd(&g_acc, 0.0f);   // read after all adds
                *out = tot * inv_n;                    // LOSS_WEIGHT = 1
                g_acc = 0.0f;
                g_done = 0;
            }
        }
    }
}

extern "C" void kernel_launch(void* const* d_in, const int* in_sizes, int n_in,
                              void* d_out, int out_size) {
    const float* preds  = (const float*)d_in[0];
    const float* scores = (const float*)d_in[1];
    const int*   labels = (const int*)d_in[2];
    const int*   batch  = (const int*)d_in[3];
    float* out = (float*)d_out;
    int n = in_sizes[1];                 // pos_scores element count = N

    k_fused<<<NB, NT>>>(preds, scores, labels, batch, out, n, 1.0f / (float)n);
}

// round 12
// speedup vs baseline: 1.0025x; 1.0025x over previous
#include <cuda_runtime.h>
#include <math.h>

#define NKEY 128            // NUM_IMGS(8) * NUM_CLASSES(16)
#define NUM_CLASSES 16
#define NB 128              // blocks (<=148 SMs -> co-resident, spin-safe)
#define NT 256              // threads per block
#define PPB 64              // points per block chunk (8192/128)
#define NSUB 8              // sub-counters per key (contention split)
#define SUBCAP 64           // slots per (key, sub); mean 8 -> +20 sigma margin
#define CAP 256             // max gathered group size (mean 64)

// ---- device scratch (no allocations; self-resetting per call) ----
__device__ float4 g_a[NKEY * NSUB * SUBCAP];   // {cx, cy, inv(2sig^2), score}
__device__ float2 g_v[NKEY * NSUB * SUBCAP];   // {cos4t, sin4t}
__device__ int    g_cnt8[NKEY * NSUB];         // zero at load; owner resets in P2
__device__ int    g_bar;                       // monotonic epoch barrier

__global__ __launch_bounds__(NT)
void k_fused(const float* __restrict__ preds,
             const float* __restrict__ scores,
             const int*   __restrict__ labels,
             const int*   __restrict__ batch,
             float* __restrict__ out, int n, float inv_n) {
    __shared__ float  sraw[PPB * 5];
    __shared__ float4 sa[CAP];
    __shared__ float2 sv[CAP];
    __shared__ int    sc[NSUB];
    __shared__ float  red[NT / 32];

    const int t    = threadIdx.x;
    const int lane = t & 31;
    const int wib  = t >> 5;
    const int b    = blockIdx.x;
    const int sub0 = b & (NSUB - 1);       // this block's sub-counter lane

    // ---- P1: precompute + slotted scatter (8-way split counters) ----
    if (b == 0 && t == 0) *out = 0.0f;     // zero output before barrier
    for (int base = b * PPB; base < n; base += NB * PPB) {
        int cnt = min(PPB, n - base);
        for (int j = t; j < cnt * 5; j += NT)       // coalesced stage
            sraw[j] = preds[base * 5 + j];
        __syncthreads();
        if (t < cnt) {
            int i = base + t;
            float cx = sraw[5 * t],     cy = sraw[5 * t + 1];
            float w  = sraw[5 * t + 2], h  = sraw[5 * t + 3];
            float th = sraw[5 * t + 4];
            float scale = fminf(fmaxf(sqrtf(w * h), 16.0f), 800.0f);
            float sig = 2.0f * scale;                      // K_RADIUS = 2
            float inv = __fdividef(1.0f, 2.0f * sig * sig);
            float sn, cs;
            __sincosf(4.0f * th, &sn, &cs);                // |arg| <= 4*pi
            int key = batch[i] * NUM_CLASSES + labels[i];
            int c   = key * NSUB + sub0;
            int slot = atomicAdd(&g_cnt8[c], 1);           // ~8 ops/addr
            if (slot < SUBCAP) {
                g_a[c * SUBCAP + slot] = make_float4(cx, cy, inv, scores[i]);
                g_v[c * SUBCAP + slot] = make_float2(cs, sn); // SCORE_ALPHA = 1
            }
        }
        __syncthreads();
    }

    // ---- monotonic epoch grid barrier (replay-safe, no reset) ----
    __threadfence();                       // publish P1 writes
    if (t == 0) {
        int ticket = atomicAdd(&g_bar, 1);
        int target = (ticket / NB + 1) * NB;
        while (*(volatile int*)&g_bar < target) { }
    }
    __syncthreads();
    __threadfence();                       // acquire P1 writes

    // ---- P2: block b sweeps key b ----
    const int mykey = b;
    if (t < NSUB) {                        // stage sub-counts, reset for replay
        int c = mykey * NSUB + t;
        int v = g_cnt8[c];
        sc[t] = min(v, SUBCAP);
        g_cnt8[c] = 0;
    }
    __syncthreads();

    // per-thread 8-entry prefix (registers)
    int off[NSUB + 1];
    off[0] = 0;
    #pragma unroll
    for (int s = 0; s < NSUB; ++s) off[s + 1] = off[s] + sc[s];
    int g = min(off[NSUB], CAP);

    // stitch the 8 dense sub-runs into contiguous smem
    for (int j = t; j < g; j += NT) {
        int s = 0;
        #pragma unroll
        for (int k = 1; k < NSUB; ++k) if (j >= off[k]) s = k;
        int src = (mykey * NSUB + s) * SUBCAP + (j - off[s]);
        sa[j] = g_a[src];
        sv[j] = g_v[src];
    }
    __syncthreads();

    // sweep: 4 threads per point, warp-uniform loops (R11 proven-safe shape)
    const int ss   = lane & 3;             // sub-thread within point
    const int gpad = (g + 7) & ~7;
    float chaos = 0.0f;
    for (int pb = wib * 8; pb < gpad; pb += (NT / 32) * 8) {
        int p = pb + (lane >> 2);
        bool valid = (p < g);
        float4 a = sa[valid ? p : 0];
        float den = 0.0f, nx = 0.0f, ny = 0.0f;
        #pragma unroll 4
        for (int j = ss; j < g; j += 4) {  // no collectives inside
            float4 bb = sa[j];
            float2 v  = sv[j];
            float dx = a.x - bb.x;
            float dy = a.y - bb.y;
            float wgt = __expf(-(dx * dx + dy * dy) * a.z) * bb.w;
            den += wgt;
            nx  += wgt * v.x;
            ny  += wgt * v.y;
        }
        #pragma unroll
        for (int o = 1; o < 4; o <<= 1) {  // fold 4 sub-threads (warp-uniform)
            den += __shfl_xor_sync(0xffffffffu, den, o);
            nx  += __shfl_xor_sync(0xffffffffu, nx, o);
            ny  += __shfl_xor_sync(0xffffffffu, ny, o);
        }
        if (valid && ss == 0)
            chaos += 1.0f - sqrtf(nx * nx + ny * ny) / den;
    }

    // ---- block reduce + direct atomic accumulate into out ----
    float v = chaos;                       // nonzero only on ss==0 lanes
    #pragma unroll
    for (int o = 16; o >= 4; o >>= 1) v += __shfl_xor_sync(0xffffffffu, v, o);
    if (lane == 0) red[wib] = v;
    __syncthreads();
    if (t < NT / 32) {
        v = red[t];
        v += __shfl_xor_sync(0xffu, v, 4);
        v += __shfl_xor_sync(0xffu, v, 2);
        v += __shfl_xor_sync(0xffu, v, 1);
        if (t == 0) atomicAdd(out, v * inv_n);   // LOSS_WEIGHT = 1
    }
}

extern "C" void kernel_launch(void* const* d_in, const int* in_sizes, int n_in,
                              void* d_out, int out_size) {
    const float* preds  = (const float*)d_in[0];
    const float* scores = (const float*)d_in[1];
    const int*   labels = (const int*)d_in[2];
    const int*   batch  = (const int*)d_in[3];
    float* out = (float*)d_out;
    int n = in_sizes[1];                 // pos_scores element count = N

    k_fused<<<NB, NT>>>(preds, scores, labels, batch, out, n, 1.0f / (float)n);
}